// round 1
// baseline (speedup 1.0000x reference)
#include <cuda_runtime.h>
#include <cuda_bf16.h>
#include <cstdint>

#define N_NODES 100000
#define N_EDGES 3200000
#define N_RELS  8
#define F_DIM   64

// Scratch: per-relation transformed features XW[r][n][f], fp32.
// 8 * 100000 * 64 * 4 B = 204.8 MB (static device array — allocation-free).
__device__ float g_XW[(size_t)N_RELS * N_NODES * F_DIM];

// ---------------------------------------------------------------------------
// Kernel 1: XW[r] = X @ W[r]   (8 small GEMMs, one relation per blockIdx.y)
// Block covers 64 rows x 64 cols. 256 threads, each computes a 4x4 tile.
// ---------------------------------------------------------------------------
__global__ __launch_bounds__(256) void xw_kernel(const float* __restrict__ X,
                                                 const float* __restrict__ W,
                                                 float* __restrict__ XW) {
    const int r  = blockIdx.y;
    const int n0 = blockIdx.x * 64;

    __shared__ float Ws[64][64];   // W[r], k-major rows
    __shared__ float Xs[64][65];   // X tile, padded to kill bank conflicts

    // Load W[r] (16 KB)
    for (int i = threadIdx.x; i < 64 * 64; i += 256) {
        Ws[i >> 6][i & 63] = W[r * 64 * 64 + i];
    }
    // Load X tile (64 rows x 64), bounds-guarded for the last block
    for (int i = threadIdx.x; i < 64 * 64; i += 256) {
        int row = i >> 6, col = i & 63;
        int n = n0 + row;
        Xs[row][col] = (n < N_NODES) ? X[(size_t)n * 64 + col] : 0.0f;
    }
    __syncthreads();

    const int ty = threadIdx.x >> 4;   // 0..15 -> 4-row group
    const int tx = threadIdx.x & 15;   // 0..15 -> 4-col group

    float acc[4][4] = {};
#pragma unroll
    for (int k = 0; k < 64; k++) {
        float xa[4], wb[4];
#pragma unroll
        for (int i = 0; i < 4; i++) xa[i] = Xs[ty * 4 + i][k];
#pragma unroll
        for (int j = 0; j < 4; j++) wb[j] = Ws[k][tx * 4 + j];
#pragma unroll
        for (int i = 0; i < 4; i++)
#pragma unroll
            for (int j = 0; j < 4; j++)
                acc[i][j] = fmaf(xa[i], wb[j], acc[i][j]);
    }

    // Store: XW[r][n][f]
    float* out_base = XW + (size_t)r * N_NODES * 64;
#pragma unroll
    for (int i = 0; i < 4; i++) {
        int n = n0 + ty * 4 + i;
        if (n < N_NODES) {
            float4 v = make_float4(acc[i][0], acc[i][1], acc[i][2], acc[i][3]);
            *reinterpret_cast<float4*>(out_base + (size_t)n * 64 + tx * 4) = v;
        }
    }
}

// ---------------------------------------------------------------------------
// Kernel 2: edge gather + scale + scatter-add.
// 16 threads per edge; each thread handles one float4 of the 64-dim feature.
// Scatter uses red.global.add.v4.f32 (no-return vector reduction, sm_90+).
// ---------------------------------------------------------------------------
__global__ __launch_bounds__(256) void edge_kernel(const float* __restrict__ XW,
                                                   const float* __restrict__ A,
                                                   const int*   __restrict__ src,
                                                   const int*   __restrict__ dst,
                                                   const int*   __restrict__ etype,
                                                   float* __restrict__ Y) {
    const long long gid = (long long)blockIdx.x * blockDim.x + threadIdx.x;
    const int e  = (int)(gid >> 4);      // edge index
    const int f4 = (int)(gid & 15);      // which float4 of the feature row
    if (e >= N_EDGES) return;

    const int s = src[e];
    const int d = dst[e];
    const int r = etype[e];
    const float a = A[e];

    const float4 v = *reinterpret_cast<const float4*>(
        XW + ((size_t)r * N_NODES + (size_t)s) * 64 + f4 * 4);

    float4 m;
    m.x = v.x * a; m.y = v.y * a; m.z = v.z * a; m.w = v.w * a;

    float* out = Y + (size_t)d * 64 + f4 * 4;
    asm volatile("red.global.add.v4.f32 [%0], {%1, %2, %3, %4};"
                 :: "l"(out), "f"(m.x), "f"(m.y), "f"(m.z), "f"(m.w)
                 : "memory");
}

// ---------------------------------------------------------------------------
// Launch: memset Y -> XW precompute -> edge scatter
// Inputs (metadata order): X, W, A, src, dst, etype
// ---------------------------------------------------------------------------
extern "C" void kernel_launch(void* const* d_in, const int* in_sizes, int n_in,
                              void* d_out, int out_size) {
    const float* X     = (const float*)d_in[0];
    const float* W     = (const float*)d_in[1];
    const float* A     = (const float*)d_in[2];
    const int*   src   = (const int*)d_in[3];
    const int*   dst   = (const int*)d_in[4];
    const int*   etype = (const int*)d_in[5];
    float* Y = (float*)d_out;

    float* XW = nullptr;
    cudaGetSymbolAddress((void**)&XW, g_XW);

    // Zero the output accumulator (graph-capturable memset node).
    cudaMemsetAsync(Y, 0, (size_t)N_NODES * F_DIM * sizeof(float), 0);

    // XW[r] = X @ W[r]
    dim3 grid_xw((N_NODES + 63) / 64, N_RELS);
    xw_kernel<<<grid_xw, 256>>>(X, W, XW);

    // Edge scatter: 16 threads per edge
    long long total_threads = (long long)N_EDGES * 16;
    int blocks = (int)((total_threads + 255) / 256);
    edge_kernel<<<blocks, 256>>>(XW, A, src, dst, etype, Y);
}

// round 2
// speedup vs baseline: 1.0672x; 1.0672x over previous
#include <cuda_runtime.h>
#include <cuda_fp16.h>
#include <cstdint>

#define N_NODES 100000
#define N_EDGES 3200000
#define N_RELS  8
#define F_DIM   64

// fp16 per-relation transformed features: 8 * 100000 * 64 * 2 B = 102.4 MB
__device__ __half g_XWh[(size_t)N_RELS * N_NODES * F_DIM];

__device__ __forceinline__ uint32_t f2tf32(float f) {
    uint32_t r;
    asm("cvt.rna.tf32.f32 %0, %1;" : "=r"(r) : "f"(f));
    return r;
}

// ---------------------------------------------------------------------------
// Kernel 1: XWh[r] = fp16(X @ W[r]) via mma.sync m16n8k8 tf32.
// Block: 256 threads (8 warps) covering 64 rows x 64 cols.
//   warp w: rows (w%4)*16 .. +16, col half (w/4)*32 .. +32
// Per warp: 4 n-tiles x 8 k-steps = 32 mma.
// ---------------------------------------------------------------------------
__global__ __launch_bounds__(256) void xw_kernel(const float* __restrict__ X,
                                                 const float* __restrict__ W,
                                                 __half* __restrict__ XWh) {
    const int r  = blockIdx.y;
    const int n0blk = blockIdx.x * 64;

    __shared__ float Xs[64][65];
    __shared__ float Ws[64][65];

    // Load W[r] (64x64) into Ws[k][n]
    for (int i = threadIdx.x; i < 64 * 64; i += 256) {
        Ws[i >> 6][i & 63] = W[r * 64 * 64 + i];
    }
    // Load X tile (64 rows), guarded
    for (int i = threadIdx.x; i < 64 * 64; i += 256) {
        int row = i >> 6, col = i & 63;
        int n = n0blk + row;
        Xs[row][col] = (n < N_NODES) ? X[(size_t)n * 64 + col] : 0.0f;
    }
    __syncthreads();

    const int warp = threadIdx.x >> 5;
    const int lane = threadIdx.x & 31;
    const int g = lane >> 2;       // groupID (0..7)
    const int t = lane & 3;        // thread in group (0..3)

    const int r0 = (warp & 3) * 16;        // row offset within 64-row tile
    const int ch = (warp >> 2) * 32;       // col half offset

    float acc[4][4];
#pragma unroll
    for (int j = 0; j < 4; j++)
#pragma unroll
        for (int c = 0; c < 4; c++) acc[j][c] = 0.0f;

#pragma unroll
    for (int kk = 0; kk < 8; kk++) {
        const int k0 = kk * 8;
        uint32_t a0 = f2tf32(Xs[r0 + g][k0 + t]);
        uint32_t a1 = f2tf32(Xs[r0 + g + 8][k0 + t]);
        uint32_t a2 = f2tf32(Xs[r0 + g][k0 + t + 4]);
        uint32_t a3 = f2tf32(Xs[r0 + g + 8][k0 + t + 4]);
#pragma unroll
        for (int j = 0; j < 4; j++) {
            const int n0 = ch + j * 8;
            uint32_t b0 = f2tf32(Ws[k0 + t][n0 + g]);
            uint32_t b1 = f2tf32(Ws[k0 + t + 4][n0 + g]);
            asm volatile(
                "mma.sync.aligned.m16n8k8.row.col.f32.tf32.tf32.f32 "
                "{%0,%1,%2,%3}, {%4,%5,%6,%7}, {%8,%9}, {%0,%1,%2,%3};"
                : "+f"(acc[j][0]), "+f"(acc[j][1]), "+f"(acc[j][2]), "+f"(acc[j][3])
                : "r"(a0), "r"(a1), "r"(a2), "r"(a3), "r"(b0), "r"(b1));
        }
    }

    // Store fp16: c0/c1 -> row g, cols 2t,2t+1 ; c2/c3 -> row g+8
    __half* base = XWh + (size_t)r * N_NODES * 64;
#pragma unroll
    for (int j = 0; j < 4; j++) {
        const int col = ch + j * 8 + 2 * t;
        const int row_a = n0blk + r0 + g;
        const int row_b = row_a + 8;
        __half2 lo = __floats2half2_rn(acc[j][0], acc[j][1]);
        __half2 hi = __floats2half2_rn(acc[j][2], acc[j][3]);
        if (row_a < N_NODES)
            *reinterpret_cast<__half2*>(base + (size_t)row_a * 64 + col) = lo;
        if (row_b < N_NODES)
            *reinterpret_cast<__half2*>(base + (size_t)row_b * 64 + col) = hi;
    }
}

// ---------------------------------------------------------------------------
// Kernel 2: edge gather (fp16) + scale + fp32 scatter-add.
// 8 threads per edge; each thread handles 8 halves (16 B) -> 2x red.v4.f32.
// ---------------------------------------------------------------------------
__global__ __launch_bounds__(256) void edge_kernel(const __half* __restrict__ XWh,
                                                   const float* __restrict__ A,
                                                   const int*   __restrict__ src,
                                                   const int*   __restrict__ dst,
                                                   const int*   __restrict__ etype,
                                                   float* __restrict__ Y) {
    const long long gid = (long long)blockIdx.x * blockDim.x + threadIdx.x;
    const int e  = (int)(gid >> 3);      // edge index
    const int f8 = (int)(gid & 7);       // which 8-half chunk
    if (e >= N_EDGES) return;

    const int s = src[e];
    const int d = dst[e];
    const int r = etype[e];
    const float a = A[e];

    const uint4 raw = *reinterpret_cast<const uint4*>(
        XWh + ((size_t)r * N_NODES + (size_t)s) * 64 + f8 * 8);

    const __half2* h = reinterpret_cast<const __half2*>(&raw);
    float2 p0 = __half22float2(h[0]);
    float2 p1 = __half22float2(h[1]);
    float2 p2 = __half22float2(h[2]);
    float2 p3 = __half22float2(h[3]);

    float m0 = p0.x * a, m1 = p0.y * a, m2 = p1.x * a, m3 = p1.y * a;
    float m4 = p2.x * a, m5 = p2.y * a, m6 = p3.x * a, m7 = p3.y * a;

    float* out = Y + (size_t)d * 64 + f8 * 8;
    asm volatile("red.global.add.v4.f32 [%0], {%1, %2, %3, %4};"
                 :: "l"(out), "f"(m0), "f"(m1), "f"(m2), "f"(m3) : "memory");
    asm volatile("red.global.add.v4.f32 [%0], {%1, %2, %3, %4};"
                 :: "l"(out + 4), "f"(m4), "f"(m5), "f"(m6), "f"(m7) : "memory");
}

// ---------------------------------------------------------------------------
extern "C" void kernel_launch(void* const* d_in, const int* in_sizes, int n_in,
                              void* d_out, int out_size) {
    const float* X     = (const float*)d_in[0];
    const float* W     = (const float*)d_in[1];
    const float* A     = (const float*)d_in[2];
    const int*   src   = (const int*)d_in[3];
    const int*   dst   = (const int*)d_in[4];
    const int*   etype = (const int*)d_in[5];
    float* Y = (float*)d_out;

    __half* XWh = nullptr;
    cudaGetSymbolAddress((void**)&XWh, g_XWh);

    cudaMemsetAsync(Y, 0, (size_t)N_NODES * F_DIM * sizeof(float), 0);

    dim3 grid_xw((N_NODES + 63) / 64, N_RELS);
    xw_kernel<<<grid_xw, 256>>>(X, W, XWh);

    long long total_threads = (long long)N_EDGES * 8;
    int blocks = (int)((total_threads + 255) / 256);
    edge_kernel<<<blocks, 256>>>(XWh, A, src, dst, etype, Y);
}